// round 11
// baseline (speedup 1.0000x reference)
#include <cuda_runtime.h>
#include <cuda_bf16.h>
#include <math.h>
#include <stdint.h>

// Problem constants
#define BB   8
#define SS   512
#define DD   512
#define DFF  2048
#define NH   8
#define NT   (BB * SS)      // 4096 rows
#define NLAY 6
#define VOCAB 32000

// ---------------- device scratch (static globals) --------------------------
__device__ float g_x  [NT * DD];
__device__ float g_y  [NT * DD];
__device__ float g_qkv[NT * 1536];
__device__ float g_t  [NT * DD];

// split-bf16 weights, transposed to [N,K]
#define W_TOTAL 60424192
__device__ __nv_bfloat16 g_wh[W_TOTAL];
__device__ __nv_bfloat16 g_wl[W_TOTAL];
// split activations
__device__ __nv_bfloat16 g_ah[NT * DFF];
__device__ __nv_bfloat16 g_al[NT * DFF];
__device__ __nv_bfloat16 g_xh[NT * DD];
__device__ __nv_bfloat16 g_xl[NT * DD];
__device__ __nv_bfloat16 g_yh[NT * DD];
__device__ __nv_bfloat16 g_yl[NT * DD];

// weight buffer offsets (elements)
#define OFF_EAW 0
#define OFF_DAW 6291456
#define OFF_EF1 18874368
#define OFF_EF2 25165824
#define OFF_DF1 31457280
#define OFF_DF2 37748736
#define OFF_FC  44040192
#define WSZ     262144

// ================= PTX helpers =============================================
__device__ __forceinline__ uint32_t s2u(const void* p) {
    uint32_t a;
    asm("{ .reg .u64 t; cvta.to.shared.u64 t, %1; cvt.u32.u64 %0, t; }"
        : "=r"(a) : "l"(p));
    return a;
}
__device__ __forceinline__ void cpa16(uint32_t s, const void* g) {
    asm volatile("cp.async.ca.shared.global [%0], [%1], 16;" :: "r"(s), "l"(g));
}
#define CP_COMMIT() asm volatile("cp.async.commit_group;" ::: "memory")
#define CP_WAIT(n)  asm volatile("cp.async.wait_group %0;" :: "n"(n) : "memory")

__device__ __forceinline__ void ldsm4(uint32_t* r, uint32_t addr) {
    asm volatile("ldmatrix.sync.aligned.m8n8.x4.shared.b16 {%0,%1,%2,%3}, [%4];"
        : "=r"(r[0]), "=r"(r[1]), "=r"(r[2]), "=r"(r[3]) : "r"(addr));
}
__device__ __forceinline__ void mma16816(float* d, const uint32_t* a, const uint32_t* b) {
    asm volatile(
        "mma.sync.aligned.m16n8k16.row.col.f32.bf16.bf16.f32 "
        "{%0,%1,%2,%3}, {%4,%5,%6,%7}, {%8,%9}, {%0,%1,%2,%3};"
        : "+f"(d[0]), "+f"(d[1]), "+f"(d[2]), "+f"(d[3])
        : "r"(a[0]), "r"(a[1]), "r"(a[2]), "r"(a[3]), "r"(b[0]), "r"(b[1]));
}

__device__ __forceinline__ void split32(float v, __nv_bfloat16& h, __nv_bfloat16& l) {
    h = __float2bfloat16(v);
    l = __float2bfloat16(v - __bfloat162float(h));
}
__device__ __forceinline__ void packsplit(float x, float y, uint32_t& hi, uint32_t& lo) {
    __nv_bfloat16 xh = __float2bfloat16(x);
    __nv_bfloat16 yh = __float2bfloat16(y);
    __nv_bfloat16 xl = __float2bfloat16(x - __bfloat162float(xh));
    __nv_bfloat16 yl = __float2bfloat16(y - __bfloat162float(yh));
    __nv_bfloat162 h2(xh, yh), l2(xl, yl);
    hi = *(uint32_t*)&h2;
    lo = *(uint32_t*)&l2;
}

// ---- narrow GEMM smem geometry (128x128, 2-stage; 2 CTAs/SM) ----
#define TS 40
#define MAT_BYTES (128 * TS * 2)      // 10240
#define STAGE_BYTES (4 * MAT_BYTES)   // 40960
#define SM_TOTAL (2 * STAGE_BYTES)    // 81920

// ---- wide GEMM smem geometry (128x256, 3-stage; 1 CTA/SM) ----
#define WA_BYTES 10240
#define WB_BYTES 20480
#define WSTAGE  (2 * WA_BYTES + 2 * WB_BYTES)  // 61440
#define WSM_TOTAL (3 * WSTAGE)        // 184320

// ================= narrow tensor-core GEMM (128x128) =======================
__global__ __launch_bounds__(256)
void gemm_tc(const __nv_bfloat16* __restrict__ Ah, const __nv_bfloat16* __restrict__ Al,
             const __nv_bfloat16* __restrict__ Bh, const __nv_bfloat16* __restrict__ Bl,
             const float* __restrict__ bias, float* __restrict__ C,
             __nv_bfloat16* __restrict__ Oh, __nv_bfloat16* __restrict__ Ol,
             int M, int N, int K, int mode)
{
    extern __shared__ char smem[];
    const uint32_t sbase = s2u(smem);
    const int tid  = threadIdx.x;
    const int lane = tid & 31;
    const int wid  = tid >> 5;
    const int wm   = wid & 1;
    const int wn   = wid >> 1;
    const int bm   = blockIdx.y * 128;
    const int bn   = blockIdx.x * 128;

    float acc[16][4];
#pragma unroll
    for (int i = 0; i < 16; i++)
#pragma unroll
        for (int j = 0; j < 4; j++) acc[i][j] = 0.0f;

    const int c0row = tid >> 2;
    const int c0col = (tid & 3) * 8;
    const int nk = K >> 5;

    auto load_stage = [&](int stage, int k0) {
        uint32_t sb = sbase + stage * STAGE_BYTES;
#pragma unroll
        for (int i = 0; i < 2; i++) {
            int row = c0row + i * 64;
            uint32_t soff = (uint32_t)((row * TS + c0col) * 2);
            size_t ga = (size_t)(bm + row) * K + k0 + c0col;
            size_t gb = (size_t)(bn + row) * K + k0 + c0col;
            cpa16(sb + 0 * MAT_BYTES + soff, Ah + ga);
            cpa16(sb + 1 * MAT_BYTES + soff, Al + ga);
            cpa16(sb + 2 * MAT_BYTES + soff, Bh + gb);
            cpa16(sb + 3 * MAT_BYTES + soff, Bl + gb);
        }
    };

    load_stage(0, 0);
    CP_COMMIT();

    const int a_row_in = lane & 15;
    const int a_col_in = (lane >> 4) * 8;
    const int b4_row   = (lane & 7) + ((lane >> 4) << 3);
    const int b4_col   = ((lane >> 3) & 1) * 8;

    for (int kt = 0; kt < nk; kt++) {
        CP_WAIT(0);
        __syncthreads();
        if (kt + 1 < nk) {
            load_stage((kt + 1) & 1, (kt + 1) << 5);
            CP_COMMIT();
        }

        uint32_t sb  = sbase + (kt & 1) * STAGE_BYTES;
        uint32_t sbk = sb + 2 * MAT_BYTES;
#pragma unroll
        for (int ks = 0; ks < 2; ks++) {
            const int kb = ks * 16;
            uint32_t bh4[4][2], bl4[4][2];
#pragma unroll
            for (int p = 0; p < 2; p++) {
                int nrow = wn * 32 + p * 16 + b4_row;
                uint32_t ad = sbk + (uint32_t)((nrow * TS + kb + b4_col) * 2);
                uint32_t t4[4];
                ldsm4(t4, ad);
                bh4[2*p][0] = t4[0]; bh4[2*p][1] = t4[1];
                bh4[2*p+1][0] = t4[2]; bh4[2*p+1][1] = t4[3];
                ldsm4(t4, ad + MAT_BYTES);
                bl4[2*p][0] = t4[0]; bl4[2*p][1] = t4[1];
                bl4[2*p+1][0] = t4[2]; bl4[2*p+1][1] = t4[3];
            }
#pragma unroll
            for (int mi = 0; mi < 4; mi++) {
                int arow = wm * 64 + mi * 16 + a_row_in;
                uint32_t ad = sb + (uint32_t)((arow * TS + kb + a_col_in) * 2);
                uint32_t ah[4], al[4];
                ldsm4(ah, ad);
                ldsm4(al, ad + MAT_BYTES);
                // product passes: same-acc MMAs separated by 4 independents
#pragma unroll
                for (int ni = 0; ni < 4; ni++)
                    mma16816(acc[mi * 4 + ni], ah, bh4[ni]);
#pragma unroll
                for (int ni = 0; ni < 4; ni++)
                    mma16816(acc[mi * 4 + ni], ah, bl4[ni]);
#pragma unroll
                for (int ni = 0; ni < 4; ni++)
                    mma16816(acc[mi * 4 + ni], al, bh4[ni]);
            }
        }
    }

    const int er = lane >> 2;
    const int ec = (lane & 3) * 2;
#pragma unroll
    for (int mi = 0; mi < 4; mi++) {
#pragma unroll
        for (int ni = 0; ni < 4; ni++) {
            const float* a4 = acc[mi * 4 + ni];
            int m0 = bm + wm * 64 + mi * 16 + er;
            int n0 = bn + wn * 32 + ni * 8 + ec;
            float bz0 = bias[n0], bz1 = bias[n0 + 1];
            float v0 = a4[0] + bz0, v1 = a4[1] + bz1;
            float v2 = a4[2] + bz0, v3 = a4[3] + bz1;
            if (mode == 0) {
                *(float2*)&C[(size_t)m0 * N + n0]       = make_float2(v0, v1);
                *(float2*)&C[(size_t)(m0 + 8) * N + n0] = make_float2(v2, v3);
            } else {
                v0 = fmaxf(v0, 0.f); v1 = fmaxf(v1, 0.f);
                v2 = fmaxf(v2, 0.f); v3 = fmaxf(v3, 0.f);
                uint32_t h01, l01, h23, l23;
                packsplit(v0, v1, h01, l01);
                packsplit(v2, v3, h23, l23);
                *(uint32_t*)&Oh[(size_t)m0 * N + n0]       = h01;
                *(uint32_t*)&Ol[(size_t)m0 * N + n0]       = l01;
                *(uint32_t*)&Oh[(size_t)(m0 + 8) * N + n0] = h23;
                *(uint32_t*)&Ol[(size_t)(m0 + 8) * N + n0] = l23;
            }
        }
    }
}

// ================= wide tensor-core GEMM (128x256, 3-stage) ================
__global__ __launch_bounds__(256)
void gemm_tcw(const __nv_bfloat16* __restrict__ Ah, const __nv_bfloat16* __restrict__ Al,
              const __nv_bfloat16* __restrict__ Bh, const __nv_bfloat16* __restrict__ Bl,
              const float* __restrict__ bias, float* __restrict__ C,
              __nv_bfloat16* __restrict__ Oh, __nv_bfloat16* __restrict__ Ol,
              int M, int N, int K, int mode)
{
    extern __shared__ char smem[];
    const uint32_t sbase = s2u(smem);
    const int tid  = threadIdx.x;
    const int lane = tid & 31;
    const int wid  = tid >> 5;
    const int wm   = wid & 1;
    const int wn   = wid >> 1;
    const int bm   = blockIdx.y * 128;
    const int bn   = blockIdx.x * 256;

    float acc[32][4];
#pragma unroll
    for (int i = 0; i < 32; i++)
#pragma unroll
        for (int j = 0; j < 4; j++) acc[i][j] = 0.0f;

    const int c0row = tid >> 2;
    const int c0col = (tid & 3) * 8;
    const int nk = K >> 5;

    auto load_stage = [&](int stage, int k0) {
        uint32_t sb = sbase + stage * WSTAGE;
#pragma unroll
        for (int i = 0; i < 2; i++) {
            int row = c0row + i * 64;
            uint32_t soff = (uint32_t)((row * TS + c0col) * 2);
            size_t ga = (size_t)(bm + row) * K + k0 + c0col;
            cpa16(sb + soff,            Ah + ga);
            cpa16(sb + WA_BYTES + soff, Al + ga);
        }
#pragma unroll
        for (int i = 0; i < 4; i++) {
            int row = c0row + i * 64;
            uint32_t soff = (uint32_t)((row * TS + c0col) * 2);
            size_t gb = (size_t)(bn + row) * K + k0 + c0col;
            cpa16(sb + 2 * WA_BYTES + soff,            Bh + gb);
            cpa16(sb + 2 * WA_BYTES + WB_BYTES + soff, Bl + gb);
        }
    };

    load_stage(0, 0);
    CP_COMMIT();
    if (1 < nk) load_stage(1, 32);
    CP_COMMIT();

    const int a_row_in = lane & 15;
    const int a_col_in = (lane >> 4) * 8;
    const int b4_row   = (lane & 7) + ((lane >> 4) << 3);
    const int b4_col   = ((lane >> 3) & 1) * 8;

    int cs = 0, ls = 2;
    for (int kt = 0; kt < nk; kt++) {
        CP_WAIT(1);
        __syncthreads();
        if (kt + 2 < nk) load_stage(ls, (kt + 2) << 5);
        CP_COMMIT();

        uint32_t sb  = sbase + cs * WSTAGE;
        uint32_t sbk = sb + 2 * WA_BYTES;
#pragma unroll
        for (int ks = 0; ks < 2; ks++) {
            const int kb = ks * 16;
            uint32_t bh4[8][2], bl4[8][2];
#pragma unroll
            for (int p = 0; p < 4; p++) {
                int nrow = wn * 64 + p * 16 + b4_row;
                uint32_t ad = sbk + (uint32_t)((nrow * TS + kb + b4_col) * 2);
                uint32_t t4[4];
                ldsm4(t4, ad);
                bh4[2*p][0] = t4[0]; bh4[2*p][1] = t4[1];
                bh4[2*p+1][0] = t4[2]; bh4[2*p+1][1] = t4[3];
                ldsm4(t4, ad + WB_BYTES);
                bl4[2*p][0] = t4[0]; bl4[2*p][1] = t4[1];
                bl4[2*p+1][0] = t4[2]; bl4[2*p+1][1] = t4[3];
            }
#pragma unroll
            for (int mi = 0; mi < 4; mi++) {
                int arow = wm * 64 + mi * 16 + a_row_in;
                uint32_t ad = sb + (uint32_t)((arow * TS + kb + a_col_in) * 2);
                uint32_t ah[4], al[4];
                ldsm4(ah, ad);
                ldsm4(al, ad + WA_BYTES);
                // product passes: same-acc MMAs separated by 8 independents
#pragma unroll
                for (int ni = 0; ni < 8; ni++)
                    mma16816(acc[mi * 8 + ni], ah, bh4[ni]);
#pragma unroll
                for (int ni = 0; ni < 8; ni++)
                    mma16816(acc[mi * 8 + ni], ah, bl4[ni]);
#pragma unroll
                for (int ni = 0; ni < 8; ni++)
                    mma16816(acc[mi * 8 + ni], al, bh4[ni]);
            }
        }
        cs = (cs + 1 == 3) ? 0 : cs + 1;
        ls = (ls + 1 == 3) ? 0 : ls + 1;
    }

    const int er = lane >> 2;
    const int ec = (lane & 3) * 2;
#pragma unroll
    for (int mi = 0; mi < 4; mi++) {
#pragma unroll
        for (int ni = 0; ni < 8; ni++) {
            const float* a4 = acc[mi * 8 + ni];
            int m0 = bm + wm * 64 + mi * 16 + er;
            int n0 = bn + wn * 64 + ni * 8 + ec;
            float bz0 = bias[n0], bz1 = bias[n0 + 1];
            float v0 = a4[0] + bz0, v1 = a4[1] + bz1;
            float v2 = a4[2] + bz0, v3 = a4[3] + bz1;
            if (mode == 0) {
                *(float2*)&C[(size_t)m0 * N + n0]       = make_float2(v0, v1);
                *(float2*)&C[(size_t)(m0 + 8) * N + n0] = make_float2(v2, v3);
            } else {
                v0 = fmaxf(v0, 0.f); v1 = fmaxf(v1, 0.f);
                v2 = fmaxf(v2, 0.f); v3 = fmaxf(v3, 0.f);
                uint32_t h01, l01, h23, l23;
                packsplit(v0, v1, h01, l01);
                packsplit(v2, v3, h23, l23);
                *(uint32_t*)&Oh[(size_t)m0 * N + n0]       = h01;
                *(uint32_t*)&Ol[(size_t)m0 * N + n0]       = l01;
                *(uint32_t*)&Oh[(size_t)(m0 + 8) * N + n0] = h23;
                *(uint32_t*)&Ol[(size_t)(m0 + 8) * N + n0] = l23;
            }
        }
    }
}

// ================= merged weight conversion (single launch) ================
#define WCONV_BLOCKS 59008
__global__ void wconv_all(const float* __restrict__ eaw, const float* __restrict__ daw,
                          const float* __restrict__ ef1, const float* __restrict__ ef2,
                          const float* __restrict__ df1, const float* __restrict__ df2,
                          const float* __restrict__ fcw,
                          __nv_bfloat16* __restrict__ wh, __nv_bfloat16* __restrict__ wl)
{
    __shared__ float tile[32][33];
    int bid = blockIdx.x;
    const float* W; size_t doff; int K, N, local;
    if (bid < 6144)       { local = bid;         W = eaw; doff = OFF_EAW; K = 512;  N = 512;  }
    else if (bid < 18432) { local = bid - 6144;  W = daw; doff = OFF_DAW; K = 512;  N = 512;  }
    else if (bid < 24576) { local = bid - 18432; W = ef1; doff = OFF_EF1; K = 512;  N = 2048; }
    else if (bid < 30720) { local = bid - 24576; W = ef2; doff = OFF_EF2; K = 2048; N = 512;  }
    else if (bid < 36864) { local = bid - 30720; W = df1; doff = OFF_DF1; K = 512;  N = 2048; }
    else if (bid < 43008) { local = bid - 36864; W = df2; doff = OFF_DF2; K = 2048; N = 512;  }
    else                  { local = bid - 43008; W = fcw; doff = OFF_FC;  K = 512;  N = 32000;}

    int tilesPerMat = (K >> 5) * (N >> 5);
    int mat  = local / tilesPerMat;
    int tile_i = local % tilesPerMat;
    int nTn  = N >> 5;
    int tk   = tile_i / nTn, tn = tile_i % nTn;
    int k0 = tk * 32, n0 = tn * 32;

    const float* Wm = W + (size_t)mat * K * N;
    __nv_bfloat16* ohm = wh + doff + (size_t)mat * K * N;
    __nv_bfloat16* olm = wl + doff + (size_t)mat * K * N;

    int tx = threadIdx.x, ty = threadIdx.y;
#pragma unroll
    for (int i = 0; i < 4; i++)
        tile[ty + i * 8][tx] = Wm[(size_t)(k0 + ty + i * 8) * N + n0 + tx];
    __syncthreads();
#pragma unroll
    for (int i = 0; i < 4; i++) {
        int n = n0 + ty + i * 8;
        int k = k0 + tx;
        float v = tile[tx][ty + i * 8];
        __nv_bfloat16 hi, lo;
        split32(v, hi, lo);
        ohm[(size_t)n * K + k] = hi;
        olm[(size_t)n * K + k] = lo;
    }
}

// ---------------- embed + positional encoding ------------------------------
__global__ void embed_kernel(const int* __restrict__ tok,
                             const float* __restrict__ emb,
                             float* __restrict__ out,
                             __nv_bfloat16* __restrict__ oh,
                             __nv_bfloat16* __restrict__ ol)
{
    int idx = blockIdx.x * blockDim.x + threadIdx.x;
    int row = idx >> 9;
    int d   = idx & 511;
    int s   = row & (SS - 1);
    int t   = tok[row];

    float freq = expf(-(float)(d & ~1) * (9.210340371976184f / 512.0f));
    float arg  = (float)s * freq;
    float pe   = (d & 1) ? cosf(arg) : sinf(arg);

    float v = emb[(size_t)t * DD + d] * 22.62741699796952f + pe;
    out[idx] = v;
    __nv_bfloat16 hi, lo;
    split32(v, hi, lo);
    oh[idx] = hi;
    ol[idx] = lo;
}

// ================= flash attention via split-bf16 mma ======================
#define L2E 1.4426950408889634f
#define ATT_SMEM (6 * 64 * 72 * 2 + 512 * 4 + 64 * 4)

__global__ __launch_bounds__(128)
void attn_mma(const float* __restrict__ Q, int qstr,
              const float* __restrict__ K, int kstr,
              const float* __restrict__ V, int vstr,
              const int* __restrict__ tok, int causal,
              __nv_bfloat16* __restrict__ Oh, __nv_bfloat16* __restrict__ Ol)
{
    extern __shared__ char sm[];
    __nv_bfloat16* Qh = (__nv_bfloat16*)sm;
    __nv_bfloat16* Ql = Qh + 64 * 72;
    __nv_bfloat16* Kh = Ql + 64 * 72;
    __nv_bfloat16* Kl = Kh + 64 * 72;
    __nv_bfloat16* Th = Kl + 64 * 72;
    __nv_bfloat16* Tl = Th + 64 * 72;
    int* kvm = (int*)(Tl + 64 * 72);
    int* tqv = kvm + 512;

    const int q0  = blockIdx.x * 64;
    const int h   = blockIdx.y;
    const int b   = blockIdx.z;
    const int tid = threadIdx.x;
    const int lane = tid & 31;
    const int w    = tid >> 5;

#pragma unroll
    for (int i = 0; i < 32; i++) {
        int e = tid + i * 128;
        int r = e >> 6, d = e & 63;
        float v = Q[(size_t)(b * SS + q0 + r) * qstr + h * 64 + d];
        __nv_bfloat16 hi, lo; split32(v, hi, lo);
        Qh[r * 72 + d] = hi; Ql[r * 72 + d] = lo;
    }
#pragma unroll
    for (int i = 0; i < 4; i++) {
        int e = tid + i * 128;
        kvm[e] = (tok[b * SS + e] != 0);
    }
    if (tid < 64) tqv[tid] = tok[b * SS + q0 + tid];
    __syncthreads();

    const uint32_t uQh = s2u(Qh), uKh = s2u(Kh), uTh = s2u(Th);
    const int a_row = lane & 15;
    const int a_col = (lane >> 4) * 8;
    const int b_row = (lane & 7) + ((lane >> 4) << 3);
    const int b_col = ((lane >> 3) & 1) * 8;
    const int c0    = 2 * (lane & 3);

    const int lrow0 = w * 16 + (lane >> 2);
    const int row0  = q0 + lrow0;
    const int row1  = row0 + 8;
    const int tq0   = tqv[lrow0];
    const int tq1   = tqv[lrow0 + 8];

    float m0 = -INFINITY, m1 = -INFINITY, l0 = 0.f, l1 = 0.f;
    float ao[8][4];
#pragma unroll
    for (int f = 0; f < 8; f++)
#pragma unroll
        for (int j = 0; j < 4; j++) ao[f][j] = 0.f;

    for (int kt = 0; kt < SS; kt += 64) {
#pragma unroll
        for (int i = 0; i < 32; i++) {
            int e = tid + i * 128;
            int kr = e >> 6, d = e & 63;
            __nv_bfloat16 hi, lo;
            float kvv = K[(size_t)(b * SS + kt + kr) * kstr + h * 64 + d];
            split32(kvv, hi, lo);
            Kh[kr * 72 + d] = hi; Kl[kr * 72 + d] = lo;
            float vv = V[(size_t)(b * SS + kt + kr) * vstr + h * 64 + d];
            split32(vv, hi, lo);
            Th[d * 72 + kr] = hi; Tl[d * 72 + kr] = lo;
        }
        __syncthreads();

        float s[8][4];
#pragma unroll
        for (int f = 0; f < 8; f++)
#pragma unroll
            for (int j = 0; j < 4; j++) s[f][j] = 0.f;

#pragma unroll
        for (int jp = 0; jp < 4; jp++) {
            uint32_t qh4[4], ql4[4];
            uint32_t qad = uQh + (uint32_t)(((w * 16 + a_row) * 72 + jp * 16 + a_col) * 2);
            ldsm4(qh4, qad);
            ldsm4(ql4, qad + 64 * 72 * 2);
#pragma unroll
            for (int kb = 0; kb < 4; kb++) {
                uint32_t bh[4], bl[4];
                uint32_t bad = uKh + (uint32_t)(((kb * 16 + b_row) * 72 + jp * 16 + b_col) * 2);
                ldsm4(bh, bad);
                ldsm4(bl, bad + 64 * 72 * 2);
                mma16816(s[kb * 2],     qh4, &bh[0]);
                mma16816(s[kb * 2 + 1], qh4, &bh[2]);
                mma16816(s[kb * 2],     qh4, &bl[0]);
                mma16816(s[kb * 2 + 1], qh4, &bl[2]);
                mma16816(s[kb * 2],     ql4, &bh[0]);
                mma16816(s[kb * 2 + 1], ql4, &bh[2]);
            }
        }

#pragma unroll
        for (int f = 0; f < 8; f++) {
            int kgA = kt + f * 8 + c0;
            int kgB = kgA + 1;
            bool v0A, v0B, v1A, v1B;
            if (causal) {
                v0A = tq0 && (kgA <= row0); v0B = tq0 && (kgB <= row0);
                v1A = tq1 && (kgA <= row1); v1B = tq1 && (kgB <= row1);
            } else {
                v0A = kvm[kgA]; v0B = kvm[kgB]; v1A = v0A; v1B = v0B;
            }
            s[f][0] = v0A ? s[f][0] * 0.125f : -1e9f;
            s[f][1] = v0B ? s[f][1] * 0.125f : -1e9f;
            s[f][2] = v1A ? s[f][2] * 0.125f : -1e9f;
            s[f][3] = v1B ? s[f][3] * 0.125f : -1e9f;
        }

        float mt0 = -INFINITY, mt1 = -INFINITY;
#pragma unroll
        for (int f = 0; f < 8; f++) {
            mt0 = fmaxf(mt0, fmaxf(s[f][0], s[f][1]));
            mt1 = fmaxf(mt1, fmaxf(s[f][2], s[f][3]));
        }
        mt0 = fmaxf(mt0, __shfl_xor_sync(0xffffffffu, mt0, 1));
        mt0 = fmaxf(mt0, __shfl_xor_sync(0xffffffffu, mt0, 2));
        mt1 = fmaxf(mt1, __shfl_xor_sync(0xffffffffu, mt1, 1));
        mt1 = fmaxf(mt1, __shfl_xor_sync(0xffffffffu, mt1, 2));

        float mn0 = fmaxf(m0, mt0), mn1 = fmaxf(m1, mt1);
        float r0 = exp2f((m0 - mn0) * L2E), r1 = exp2f((m1 - mn1) * L2E);
        m0 = mn0; m1 = mn1;

        uint32_t pah[4][4], pal[4][4];
        float sum0 = 0.f, sum1 = 0.f;
#pragma unroll
        for (int f = 0; f < 8; f++) {
            float p0 = exp2f((s[f][0] - m0) * L2E);
            float p1 = exp2f((s[f][1] - m0) * L2E);
            float p2 = exp2f((s[f][2] - m1) * L2E);
            float p3 = exp2f((s[f][3] - m1) * L2E);
            sum0 += p0 + p1; sum1 += p2 + p3;
            int jp = f >> 1;
            if ((f & 1) == 0) {
                packsplit(p0, p1, pah[jp][0], pal[jp][0]);
                packsplit(p2, p3, pah[jp][1], pal[jp][1]);
            } else {
                packsplit(p0, p1, pah[jp][2], pal[jp][2]);
                packsplit(p2, p3, pah[jp][3], pal[jp][3]);
            }
        }
        sum0 += __shfl_xor_sync(0xffffffffu, sum0, 1);
        sum0 += __shfl_xor_sync(0xffffffffu, sum0, 2);
        sum1 += __shfl_xor_sync(0xffffffffu, sum1, 1);
        sum1 += __shfl_xor_sync(0xffffffffu, sum1, 2);
        l0 = l0 * r0 + sum0;
        l1 = l1 * r1 + sum1;

#pragma unroll
        for (int f = 0; f < 8; f++) {
            ao[f][0] *= r0; ao[f][1] *= r0;
            ao[f][2] *= r1; ao[f][3] *= r1;
        }

#pragma unroll
        for (int jp = 0; jp < 4; jp++) {
#pragma unroll
            for (int db = 0; db < 4; db++) {
                uint32_t bh[4], bl[4];
                uint32_t bad = uTh + (uint32_t)(((db * 16 + b_row) * 72 + jp * 16 + b_col) * 2);
                ldsm4(bh, bad);
                ldsm4(bl, bad + 64 * 72 * 2);
                mma16816(ao[db * 2],     pah[jp], &bh[0]);
                mma16816(ao[db * 2 + 1], pah[jp], &bh[2]);
                mma16816(ao[db * 2],     pah[jp], &bl[0]);
                mma16816(ao[db * 2 + 1], pah[jp], &bl[2]);
                mma16816(ao[db * 2],     pal[jp], &bh[0]);
                mma16816(ao[db * 2 + 1], pal[jp], &bh[2]);
            }
        }
        __syncthreads();
    }

    float il0 = 1.f / l0, il1 = 1.f / l1;
    size_t gr0 = (size_t)(b * SS + row0) * DD + h * 64;
    size_t gr1 = (size_t)(b * SS + row1) * DD + h * 64;
#pragma unroll
    for (int f = 0; f < 8; f++) {
        int d = f * 8 + c0;
        uint32_t h01, l01, h23, l23;
        packsplit(ao[f][0] * il0, ao[f][1] * il0, h01, l01);
        packsplit(ao[f][2] * il1, ao[f][3] * il1, h23, l23);
        *(uint32_t*)&Oh[gr0 + d] = h01;
        *(uint32_t*)&Ol[gr0 + d] = l01;
        *(uint32_t*)&Oh[gr1 + d] = h23;
        *(uint32_t*)&Ol[gr1 + d] = l23;
    }
}

// ---------------- residual + LayerNorm: warp-per-row -----------------------
__global__ __launch_bounds__(256)
void ln_res_kernel(const float* __restrict__ t, float* __restrict__ x,
                   const float* __restrict__ s, const float* __restrict__ b,
                   __nv_bfloat16* __restrict__ xh, __nv_bfloat16* __restrict__ xl)
{
    const int w    = threadIdx.x >> 5;
    const int lane = threadIdx.x & 31;
    const int row  = blockIdx.x * 8 + w;

    const float4* tp = (const float4*)(t + (size_t)row * 512);
    float4*       xp = (float4*)(x + (size_t)row * 512);
    const float4* sp = (const float4*)s;
    const float4* bp = (const float4*)b;

    float4 u[4];
    float sum = 0.f;
#pragma unroll
    for (int j = 0; j < 4; j++) {
        float4 a = tp[j * 32 + lane];
        float4 c = xp[j * 32 + lane];
        u[j] = make_float4(a.x + c.x, a.y + c.y, a.z + c.z, a.w + c.w);
        sum += u[j].x + u[j].y + u[j].z + u[j].w;
    }
#pragma unroll
    for (int o = 16; o; o >>= 1) sum += __shfl_xor_sync(0xffffffffu, sum, o);
    float mean = sum * (1.0f / 512.0f);

    float sq = 0.f;
#pragma unroll
    for (int j = 0; j < 4; j++) {
        float dx = u[j].x - mean, dy = u[j].y - mean;
        float dz = u[j].z - mean, dw = u[j].w - mean;
        sq += dx * dx + dy * dy + dz * dz + dw * dw;
    }
#pragma unroll
    for (int o = 16; o; o >>= 1) sq += __shfl_xor_sync(0xffffffffu, sq, o);
    float inv = rsqrtf(sq * (1.0f / 512.0f) + 1e-5f);

#pragma unroll
    for (int j = 0; j < 4; j++) {
        float4 sc = sp[j * 32 + lane];
        float4 bb = bp[j * 32 + lane];
        float4 o;
        o.x = (u[j].x - mean) * inv * sc.x + bb.x;
        o.y = (u[j].y - mean) * inv * sc.y + bb.y;
        o.z = (u[j].z - mean) * inv * sc.z + bb.z;
        o.w = (u[j].w - mean) * inv * sc.w + bb.w;
        xp[j * 32 + lane] = o;
        uint32_t h01, l01, h23, l23;
        packsplit(o.x, o.y, h01, l01);
        packsplit(o.z, o.w, h23, l23);
        size_t e = (size_t)row * 512 + (size_t)(j * 32 + lane) * 4;
        *(uint2*)&xh[e] = make_uint2(h01, h23);
        *(uint2*)&xl[e] = make_uint2(l01, l23);
    }
}

// ---------------- host orchestration ---------------------------------------
static __nv_bfloat16 *h_wh, *h_wl, *h_ah, *h_al, *h_xh, *h_xl, *h_yh, *h_yl;

static inline void run_gemm(const __nv_bfloat16* Ah, const __nv_bfloat16* Al,
                            size_t woff, const float* bias, float* C,
                            int M, int N, int K)
{
    if ((N & 255) == 0 && N >= 1024) {
        dim3 g(N / 256, M / 128);
        gemm_tcw<<<g, 256, WSM_TOTAL>>>(Ah, Al, h_wh + woff, h_wl + woff, bias, C,
                                        nullptr, nullptr, M, N, K, 0);
    } else {
        dim3 g(N / 128, M / 128);
        gemm_tc<<<g, 256, SM_TOTAL>>>(Ah, Al, h_wh + woff, h_wl + woff, bias, C,
                                      nullptr, nullptr, M, N, K, 0);
    }
}
static inline void run_gemm_relu_split(const __nv_bfloat16* Ah, const __nv_bfloat16* Al,
                                       size_t woff, const float* bias,
                                       __nv_bfloat16* Oh, __nv_bfloat16* Ol,
                                       int M, int N, int K)
{
    if ((N & 255) == 0 && N >= 1024) {
        dim3 g(N / 256, M / 128);
        gemm_tcw<<<g, 256, WSM_TOTAL>>>(Ah, Al, h_wh + woff, h_wl + woff, bias, nullptr,
                                        Oh, Ol, M, N, K, 1);
    } else {
        dim3 g(N / 128, M / 128);
        gemm_tc<<<g, 256, SM_TOTAL>>>(Ah, Al, h_wh + woff, h_wl + woff, bias, nullptr,
                                      Oh, Ol, M, N, K, 1);
    }
}

extern "C" void kernel_launch(void* const* d_in, const int* in_sizes, int n_in,
                              void* d_out, int out_size)
{
    const int*   src     = (const int*)  d_in[0];
    const int*   tgt     = (const int*)  d_in[1];
    const float* src_emb = (const float*)d_in[2];
    const float* tgt_emb = (const float*)d_in[3];
    const float* eaw     = (const float*)d_in[4];
    const float* eab     = (const float*)d_in[5];
    const float* els     = (const float*)d_in[6];
    const float* elb     = (const float*)d_in[7];
    const float* ef1     = (const float*)d_in[8];
    const float* eb1     = (const float*)d_in[9];
    const float* ef2     = (const float*)d_in[10];
    const float* eb2     = (const float*)d_in[11];
    const float* daw     = (const float*)d_in[12];
    const float* dab     = (const float*)d_in[13];
    const float* dls     = (const float*)d_in[14];
    const float* dlb     = (const float*)d_in[15];
    const float* df1     = (const float*)d_in[16];
    const float* db1     = (const float*)d_in[17];
    const float* df2     = (const float*)d_in[18];
    const float* db2     = (const float*)d_in[19];
    const float* fcw     = (const float*)d_in[20];
    const float* fcb     = (const float*)d_in[21];
    float*       out     = (float*)d_out;

    float *x, *y, *qkv, *t;
    cudaGetSymbolAddress((void**)&x,   g_x);
    cudaGetSymbolAddress((void**)&y,   g_y);
    cudaGetSymbolAddress((void**)&qkv, g_qkv);
    cudaGetSymbolAddress((void**)&t,   g_t);
    cudaGetSymbolAddress((void**)&h_wh, g_wh);
    cudaGetSymbolAddress((void**)&h_wl, g_wl);
    cudaGetSymbolAddress((void**)&h_ah, g_ah);
    cudaGetSymbolAddress((void**)&h_al, g_al);
    cudaGetSymbolAddress((void**)&h_xh, g_xh);
    cudaGetSymbolAddress((void**)&h_xl, g_xl);
    cudaGetSymbolAddress((void**)&h_yh, g_yh);
    cudaGetSymbolAddress((void**)&h_yl, g_yl);

    cudaFuncSetAttribute(gemm_tc,  cudaFuncAttributeMaxDynamicSharedMemorySize, SM_TOTAL);
    cudaFuncSetAttribute(gemm_tcw, cudaFuncAttributeMaxDynamicSharedMemorySize, WSM_TOTAL);
    cudaFuncSetAttribute(attn_mma, cudaFuncAttributeMaxDynamicSharedMemorySize, ATT_SMEM);

    // ---- weight prep: ONE launch ----
    {
        dim3 bdim(32, 8);
        wconv_all<<<WCONV_BLOCKS, bdim>>>(eaw, daw, ef1, ef2, df1, df2, fcw, h_wh, h_wl);
    }

    // embeddings + positional encoding (+ split)
    embed_kernel<<<(NT * DD) / 256, 256>>>(src, src_emb, x, h_xh, h_xl);
    embed_kernel<<<(NT * DD) / 256, 256>>>(tgt, tgt_emb, y, h_yh, h_yl);

    dim3 ag(SS / 64, NH, BB);
    float* kvbuf = qkv + (size_t)NT * 512;

    // ---------------- encoder ----------------
    for (int L = 0; L < NLAY; L++) {
        size_t w0 = OFF_EAW + (size_t)(L * 4) * WSZ;
        const float* Bz = eab + (size_t)L * 4 * DD;

        run_gemm(h_xh, h_xl, w0, Bz, qkv, NT, 1536, DD);
        attn_mma<<<ag, 128, ATT_SMEM>>>(qkv, 1536, qkv + 512, 1536, qkv + 1024, 1536,
                                        src, 0, h_ah, h_al);
        run_gemm(h_ah, h_al, w0 + 3 * WSZ, Bz + 3 * DD, t, NT, DD, DD);
        ln_res_kernel<<<NT / 8, 256>>>(t, x, els + (size_t)(L * 2 + 0) * DD,
                                       elb + (size_t)(L * 2 + 0) * DD, h_xh, h_xl);

        run_gemm_relu_split(h_xh, h_xl, OFF_EF1 + (size_t)L * DD * DFF,
                            eb1 + (size_t)L * DFF, h_ah, h_al, NT, DFF, DD);
        run_gemm(h_ah, h_al, OFF_EF2 + (size_t)L * DD * DFF, eb2 + (size_t)L * DD,
                 t, NT, DD, DFF);
        ln_res_kernel<<<NT / 8, 256>>>(t, x, els + (size_t)(L * 2 + 1) * DD,
                                       elb + (size_t)(L * 2 + 1) * DD, h_xh, h_xl);
    }

    // ---------------- decoder ----------------
    for (int L = 0; L < NLAY; L++) {
        size_t w0 = OFF_DAW + (size_t)(L * 8) * WSZ;
        const float* Bz = dab + (size_t)L * 8 * DD;

        run_gemm(h_yh, h_yl, w0, Bz, qkv, NT, 1536, DD);
        attn_mma<<<ag, 128, ATT_SMEM>>>(qkv, 1536, qkv + 512, 1536, qkv + 1024, 1536,
                                        tgt, 1, h_ah, h_al);
        run_gemm(h_ah, h_al, w0 + 3 * WSZ, Bz + 3 * DD, t, NT, DD, DD);
        ln_res_kernel<<<NT / 8, 256>>>(t, y, dls + (size_t)(L * 3 + 0) * DD,
                                       dlb + (size_t)(L * 3 + 0) * DD, h_yh, h_yl);

        run_gemm(h_yh, h_yl, w0 + 4 * WSZ, Bz + 4 * DD, qkv, NT, DD, DD);
        run_gemm(h_xh, h_xl, w0 + 5 * WSZ, Bz + 5 * DD, kvbuf, NT, 1024, DD);
        attn_mma<<<ag, 128, ATT_SMEM>>>(qkv, 512, kvbuf, 1024, kvbuf + 512, 1024,
                                        src, 0, h_ah, h_al);
        run_gemm(h_ah, h_al, w0 + 7 * WSZ, Bz + 7 * DD, t, NT, DD, DD);
        ln_res_kernel<<<NT / 8, 256>>>(t, y, dls + (size_t)(L * 3 + 1) * DD,
                                       dlb + (size_t)(L * 3 + 1) * DD, h_yh, h_yl);

        run_gemm_relu_split(h_yh, h_yl, OFF_DF1 + (size_t)L * DD * DFF,
                            db1 + (size_t)L * DFF, h_ah, h_al, NT, DFF, DD);
        run_gemm(h_ah, h_al, OFF_DF2 + (size_t)L * DD * DFF, db2 + (size_t)L * DD,
                 t, NT, DD, DFF);
        ln_res_kernel<<<NT / 8, 256>>>(t, y, dls + (size_t)(L * 3 + 2) * DD,
                                       dlb + (size_t)(L * 3 + 2) * DD, h_yh, h_yl);
    }

    // final projection to vocab
    run_gemm(h_yh, h_yl, OFF_FC, fcb, out, NT, VOCAB, DD);
}

// round 12
// speedup vs baseline: 1.2983x; 1.2983x over previous
#include <cuda_runtime.h>
#include <cuda_bf16.h>
#include <cuda_fp16.h>
#include <math.h>
#include <stdint.h>

// Problem constants
#define BB   8
#define SS   512
#define DD   512
#define DFF  2048
#define NH   8
#define NT   (BB * SS)      // 4096 rows
#define NLAY 6
#define VOCAB 32000

// ---------------- device scratch (static globals) --------------------------
__device__ float g_x  [NT * DD];
__device__ float g_y  [NT * DD];
__device__ float g_qkv[NT * 1536];
__device__ float g_t  [NT * DD];

// split-fp16 weights, transposed to [N,K]
#define W_TOTAL 60424192
__device__ __half g_wh[W_TOTAL];
__device__ __half g_wl[W_TOTAL];
// single-fp16 activations
__device__ __half g_ah[NT * DFF];   // ffn-mid / attn-out
__device__ __half g_xh[NT * DD];    // encoder stream
__device__ __half g_yh[NT * DD];    // decoder stream

// weight buffer offsets (elements)
#define OFF_EAW 0
#define OFF_DAW 6291456
#define OFF_EF1 18874368
#define OFF_EF2 25165824
#define OFF_DF1 31457280
#define OFF_DF2 37748736
#define OFF_FC  44040192
#define WSZ     262144

// ================= PTX helpers =============================================
__device__ __forceinline__ uint32_t s2u(const void* p) {
    uint32_t a;
    asm("{ .reg .u64 t; cvta.to.shared.u64 t, %1; cvt.u32.u64 %0, t; }"
        : "=r"(a) : "l"(p));
    return a;
}
__device__ __forceinline__ void cpa16(uint32_t s, const void* g) {
    asm volatile("cp.async.ca.shared.global [%0], [%1], 16;" :: "r"(s), "l"(g));
}
#define CP_COMMIT() asm volatile("cp.async.commit_group;" ::: "memory")
#define CP_WAIT(n)  asm volatile("cp.async.wait_group %0;" :: "n"(n) : "memory")

__device__ __forceinline__ void ldsm4(uint32_t* r, uint32_t addr) {
    asm volatile("ldmatrix.sync.aligned.m8n8.x4.shared.b16 {%0,%1,%2,%3}, [%4];"
        : "=r"(r[0]), "=r"(r[1]), "=r"(r[2]), "=r"(r[3]) : "r"(addr));
}
// bf16 mma (attention)
__device__ __forceinline__ void mma16816(float* d, const uint32_t* a, const uint32_t* b) {
    asm volatile(
        "mma.sync.aligned.m16n8k16.row.col.f32.bf16.bf16.f32 "
        "{%0,%1,%2,%3}, {%4,%5,%6,%7}, {%8,%9}, {%0,%1,%2,%3};"
        : "+f"(d[0]), "+f"(d[1]), "+f"(d[2]), "+f"(d[3])
        : "r"(a[0]), "r"(a[1]), "r"(a[2]), "r"(a[3]), "r"(b[0]), "r"(b[1]));
}
// fp16 mma (linear gemms)
__device__ __forceinline__ void mma16816h(float* d, const uint32_t* a, const uint32_t* b) {
    asm volatile(
        "mma.sync.aligned.m16n8k16.row.col.f32.f16.f16.f32 "
        "{%0,%1,%2,%3}, {%4,%5,%6,%7}, {%8,%9}, {%0,%1,%2,%3};"
        : "+f"(d[0]), "+f"(d[1]), "+f"(d[2]), "+f"(d[3])
        : "r"(a[0]), "r"(a[1]), "r"(a[2]), "r"(a[3]), "r"(b[0]), "r"(b[1]));
}

// bf16 split helpers (attention internals)
__device__ __forceinline__ void split32(float v, __nv_bfloat16& h, __nv_bfloat16& l) {
    h = __float2bfloat16(v);
    l = __float2bfloat16(v - __bfloat162float(h));
}
__device__ __forceinline__ void packsplit(float x, float y, uint32_t& hi, uint32_t& lo) {
    __nv_bfloat16 xh = __float2bfloat16(x);
    __nv_bfloat16 yh = __float2bfloat16(y);
    __nv_bfloat16 xl = __float2bfloat16(x - __bfloat162float(xh));
    __nv_bfloat16 yl = __float2bfloat16(y - __bfloat162float(yh));
    __nv_bfloat162 h2(xh, yh), l2(xl, yl);
    hi = *(uint32_t*)&h2;
    lo = *(uint32_t*)&l2;
}
// fp16 helpers
__device__ __forceinline__ uint32_t pack2h(float x, float y) {
    __half2 h = __floats2half2_rn(x, y);
    return *(uint32_t*)&h;
}
__device__ __forceinline__ void wsplit(float v, __half& h, __half& l) {
    h = __float2half_rn(v);
    l = __float2half_rn(v - __half2float(h));
}

// ---- narrow GEMM smem geometry (128x128, 2-stage) ----
#define TS 40
#define MAT_BYTES (128 * TS * 2)      // 10240
#define STAGE_BYTES (3 * MAT_BYTES)   // 30720: A, Bh, Bl
#define SM_TOTAL (2 * STAGE_BYTES)    // 61440

// ---- wide GEMM smem geometry (128x256, 3-stage) ----
#define WA_BYTES 10240
#define WB_BYTES 20480
#define WSTAGE  (WA_BYTES + 2 * WB_BYTES)      // 51200
#define WSM_TOTAL (3 * WSTAGE)                 // 153600

// ================= narrow tensor-core GEMM (128x128) =======================
// C = A[M,K](fp16) @ (Bh+Bl)[N,K]^T + bias.
// mode 0: fp32 -> C.  mode 1: relu, fp16 -> Oh.
__global__ __launch_bounds__(256)
void gemm_tc(const __half* __restrict__ A,
             const __half* __restrict__ Bh, const __half* __restrict__ Bl,
             const float* __restrict__ bias, float* __restrict__ C,
             __half* __restrict__ Oh,
             int M, int N, int K, int mode)
{
    extern __shared__ char smem[];
    const uint32_t sbase = s2u(smem);
    const int tid  = threadIdx.x;
    const int lane = tid & 31;
    const int wid  = tid >> 5;
    const int wm   = wid & 1;
    const int wn   = wid >> 1;
    const int bm   = blockIdx.y * 128;
    const int bn   = blockIdx.x * 128;

    float acc[16][4];
#pragma unroll
    for (int i = 0; i < 16; i++)
#pragma unroll
        for (int j = 0; j < 4; j++) acc[i][j] = 0.0f;

    const int c0row = tid >> 2;
    const int c0col = (tid & 3) * 8;
    const int nk = K >> 5;

    auto load_stage = [&](int stage, int k0) {
        uint32_t sb = sbase + stage * STAGE_BYTES;
#pragma unroll
        for (int i = 0; i < 2; i++) {
            int row = c0row + i * 64;
            uint32_t soff = (uint32_t)((row * TS + c0col) * 2);
            size_t ga = (size_t)(bm + row) * K + k0 + c0col;
            size_t gb = (size_t)(bn + row) * K + k0 + c0col;
            cpa16(sb + soff,                 A  + ga);
            cpa16(sb + 1 * MAT_BYTES + soff, Bh + gb);
            cpa16(sb + 2 * MAT_BYTES + soff, Bl + gb);
        }
    };

    load_stage(0, 0);
    CP_COMMIT();

    const int a_row_in = lane & 15;
    const int a_col_in = (lane >> 4) * 8;
    const int b4_row   = (lane & 7) + ((lane >> 4) << 3);
    const int b4_col   = ((lane >> 3) & 1) * 8;

    for (int kt = 0; kt < nk; kt++) {
        CP_WAIT(0);
        __syncthreads();
        if (kt + 1 < nk) {
            load_stage((kt + 1) & 1, (kt + 1) << 5);
            CP_COMMIT();
        }

        uint32_t sb  = sbase + (kt & 1) * STAGE_BYTES;
        uint32_t sbk = sb + 1 * MAT_BYTES;
#pragma unroll
        for (int ks = 0; ks < 2; ks++) {
            const int kb = ks * 16;
            uint32_t bh4[4][2], bl4[4][2];
#pragma unroll
            for (int p = 0; p < 2; p++) {
                int nrow = wn * 32 + p * 16 + b4_row;
                uint32_t ad = sbk + (uint32_t)((nrow * TS + kb + b4_col) * 2);
                uint32_t t4[4];
                ldsm4(t4, ad);
                bh4[2*p][0] = t4[0]; bh4[2*p][1] = t4[1];
                bh4[2*p+1][0] = t4[2]; bh4[2*p+1][1] = t4[3];
                ldsm4(t4, ad + MAT_BYTES);
                bl4[2*p][0] = t4[0]; bl4[2*p][1] = t4[1];
                bl4[2*p+1][0] = t4[2]; bl4[2*p+1][1] = t4[3];
            }
#pragma unroll
            for (int mi = 0; mi < 4; mi++) {
                int arow = wm * 64 + mi * 16 + a_row_in;
                uint32_t ad = sb + (uint32_t)((arow * TS + kb + a_col_in) * 2);
                uint32_t ah[4];
                ldsm4(ah, ad);
#pragma unroll
                for (int ni = 0; ni < 4; ni++)
                    mma16816h(acc[mi * 4 + ni], ah, bh4[ni]);
#pragma unroll
                for (int ni = 0; ni < 4; ni++)
                    mma16816h(acc[mi * 4 + ni], ah, bl4[ni]);
            }
        }
    }

    const int er = lane >> 2;
    const int ec = (lane & 3) * 2;
#pragma unroll
    for (int mi = 0; mi < 4; mi++) {
#pragma unroll
        for (int ni = 0; ni < 4; ni++) {
            const float* a4 = acc[mi * 4 + ni];
            int m0 = bm + wm * 64 + mi * 16 + er;
            int n0 = bn + wn * 32 + ni * 8 + ec;
            float bz0 = bias[n0], bz1 = bias[n0 + 1];
            float v0 = a4[0] + bz0, v1 = a4[1] + bz1;
            float v2 = a4[2] + bz0, v3 = a4[3] + bz1;
            if (mode == 0) {
                *(float2*)&C[(size_t)m0 * N + n0]       = make_float2(v0, v1);
                *(float2*)&C[(size_t)(m0 + 8) * N + n0] = make_float2(v2, v3);
            } else {
                v0 = fmaxf(v0, 0.f); v1 = fmaxf(v1, 0.f);
                v2 = fmaxf(v2, 0.f); v3 = fmaxf(v3, 0.f);
                *(uint32_t*)&Oh[(size_t)m0 * N + n0]       = pack2h(v0, v1);
                *(uint32_t*)&Oh[(size_t)(m0 + 8) * N + n0] = pack2h(v2, v3);
            }
        }
    }
}

// ================= wide tensor-core GEMM (128x256, 3-stage) ================
__global__ __launch_bounds__(256)
void gemm_tcw(const __half* __restrict__ A,
              const __half* __restrict__ Bh, const __half* __restrict__ Bl,
              const float* __restrict__ bias, float* __restrict__ C,
              __half* __restrict__ Oh,
              int M, int N, int K, int mode)
{
    extern __shared__ char smem[];
    const uint32_t sbase = s2u(smem);
    const int tid  = threadIdx.x;
    const int lane = tid & 31;
    const int wid  = tid >> 5;
    const int wm   = wid & 1;
    const int wn   = wid >> 1;
    const int bm   = blockIdx.y * 128;
    const int bn   = blockIdx.x * 256;

    float acc[32][4];
#pragma unroll
    for (int i = 0; i < 32; i++)
#pragma unroll
        for (int j = 0; j < 4; j++) acc[i][j] = 0.0f;

    const int c0row = tid >> 2;
    const int c0col = (tid & 3) * 8;
    const int nk = K >> 5;

    auto load_stage = [&](int stage, int k0) {
        uint32_t sb = sbase + stage * WSTAGE;
#pragma unroll
        for (int i = 0; i < 2; i++) {
            int row = c0row + i * 64;
            uint32_t soff = (uint32_t)((row * TS + c0col) * 2);
            size_t ga = (size_t)(bm + row) * K + k0 + c0col;
            cpa16(sb + soff, A + ga);
        }
#pragma unroll
        for (int i = 0; i < 4; i++) {
            int row = c0row + i * 64;
            uint32_t soff = (uint32_t)((row * TS + c0col) * 2);
            size_t gb = (size_t)(bn + row) * K + k0 + c0col;
            cpa16(sb + WA_BYTES + soff,            Bh + gb);
            cpa16(sb + WA_BYTES + WB_BYTES + soff, Bl + gb);
        }
    };

    load_stage(0, 0);
    CP_COMMIT();
    if (1 < nk) load_stage(1, 32);
    CP_COMMIT();

    const int a_row_in = lane & 15;
    const int a_col_in = (lane >> 4) * 8;
    const int b4_row   = (lane & 7) + ((lane >> 4) << 3);
    const int b4_col   = ((lane >> 3) & 1) * 8;

    int cs = 0, ls = 2;
    for (int kt = 0; kt < nk; kt++) {
        CP_WAIT(1);
        __syncthreads();
        if (kt + 2 < nk) load_stage(ls, (kt + 2) << 5);
        CP_COMMIT();

        uint32_t sb  = sbase + cs * WSTAGE;
        uint32_t sbk = sb + WA_BYTES;
#pragma unroll
        for (int ks = 0; ks < 2; ks++) {
            const int kb = ks * 16;
            uint32_t bh4[8][2], bl4[8][2];
#pragma unroll
            for (int p = 0; p < 4; p++) {
                int nrow = wn * 64 + p * 16 + b4_row;
                uint32_t ad = sbk + (uint32_t)((nrow * TS + kb + b4_col) * 2);
                uint32_t t4[4];
                ldsm4(t4, ad);
                bh4[2*p][0] = t4[0]; bh4[2*p][1] = t4[1];
                bh4[2*p+1][0] = t4[2]; bh4[2*p+1][1] = t4[3];
                ldsm4(t4, ad + WB_BYTES);
                bl4[2*p][0] = t4[0]; bl4[2*p][1] = t4[1];
                bl4[2*p+1][0] = t4[2]; bl4[2*p+1][1] = t4[3];
            }
#pragma unroll
            for (int mi = 0; mi < 4; mi++) {
                int arow = wm * 64 + mi * 16 + a_row_in;
                uint32_t ad = sb + (uint32_t)((arow * TS + kb + a_col_in) * 2);
                uint32_t ah[4];
                ldsm4(ah, ad);
#pragma unroll
                for (int ni = 0; ni < 8; ni++)
                    mma16816h(acc[mi * 8 + ni], ah, bh4[ni]);
#pragma unroll
                for (int ni = 0; ni < 8; ni++)
                    mma16816h(acc[mi * 8 + ni], ah, bl4[ni]);
            }
        }
        cs = (cs + 1 == 3) ? 0 : cs + 1;
        ls = (ls + 1 == 3) ? 0 : ls + 1;
    }

    const int er = lane >> 2;
    const int ec = (lane & 3) * 2;
#pragma unroll
    for (int mi = 0; mi < 4; mi++) {
#pragma unroll
        for (int ni = 0; ni < 8; ni++) {
            const float* a4 = acc[mi * 8 + ni];
            int m0 = bm + wm * 64 + mi * 16 + er;
            int n0 = bn + wn * 64 + ni * 8 + ec;
            float bz0 = bias[n0], bz1 = bias[n0 + 1];
            float v0 = a4[0] + bz0, v1 = a4[1] + bz1;
            float v2 = a4[2] + bz0, v3 = a4[3] + bz1;
            if (mode == 0) {
                *(float2*)&C[(size_t)m0 * N + n0]       = make_float2(v0, v1);
                *(float2*)&C[(size_t)(m0 + 8) * N + n0] = make_float2(v2, v3);
            } else {
                v0 = fmaxf(v0, 0.f); v1 = fmaxf(v1, 0.f);
                v2 = fmaxf(v2, 0.f); v3 = fmaxf(v3, 0.f);
                *(uint32_t*)&Oh[(size_t)m0 * N + n0]       = pack2h(v0, v1);
                *(uint32_t*)&Oh[(size_t)(m0 + 8) * N + n0] = pack2h(v2, v3);
            }
        }
    }
}

// ================= merged weight conversion (single launch) ================
#define WCONV_BLOCKS 59008
__global__ void wconv_all(const float* __restrict__ eaw, const float* __restrict__ daw,
                          const float* __restrict__ ef1, const float* __restrict__ ef2,
                          const float* __restrict__ df1, const float* __restrict__ df2,
                          const float* __restrict__ fcw,
                          __half* __restrict__ wh, __half* __restrict__ wl)
{
    __shared__ float tile[32][33];
    int bid = blockIdx.x;
    const float* W; size_t doff; int K, N, local;
    if (bid < 6144)       { local = bid;         W = eaw; doff = OFF_EAW; K = 512;  N = 512;  }
    else if (bid < 18432) { local = bid - 6144;  W = daw; doff = OFF_DAW; K = 512;  N = 512;  }
    else if (bid < 24576) { local = bid - 18432; W = ef1; doff = OFF_EF1; K = 512;  N = 2048; }
    else if (bid < 30720) { local = bid - 24576; W = ef2; doff = OFF_EF2; K = 2048; N = 512;  }
    else if (bid < 36864) { local = bid - 30720; W = df1; doff = OFF_DF1; K = 512;  N = 2048; }
    else if (bid < 43008) { local = bid - 36864; W = df2; doff = OFF_DF2; K = 2048; N = 512;  }
    else                  { local = bid - 43008; W = fcw; doff = OFF_FC;  K = 512;  N = 32000;}

    int tilesPerMat = (K >> 5) * (N >> 5);
    int mat  = local / tilesPerMat;
    int tile_i = local % tilesPerMat;
    int nTn  = N >> 5;
    int tk   = tile_i / nTn, tn = tile_i % nTn;
    int k0 = tk * 32, n0 = tn * 32;

    const float* Wm = W + (size_t)mat * K * N;
    __half* ohm = wh + doff + (size_t)mat * K * N;
    __half* olm = wl + doff + (size_t)mat * K * N;

    int tx = threadIdx.x, ty = threadIdx.y;
#pragma unroll
    for (int i = 0; i < 4; i++)
        tile[ty + i * 8][tx] = Wm[(size_t)(k0 + ty + i * 8) * N + n0 + tx];
    __syncthreads();
#pragma unroll
    for (int i = 0; i < 4; i++) {
        int n = n0 + ty + i * 8;
        int k = k0 + tx;
        float v = tile[tx][ty + i * 8];
        __half hi, lo;
        wsplit(v, hi, lo);
        ohm[(size_t)n * K + k] = hi;
        olm[(size_t)n * K + k] = lo;
    }
}

// ---------------- embed + positional encoding ------------------------------
__global__ void embed_kernel(const int* __restrict__ tok,
                             const float* __restrict__ emb,
                             float* __restrict__ out,
                             __half* __restrict__ oh)
{
    int idx = blockIdx.x * blockDim.x + threadIdx.x;
    int row = idx >> 9;
    int d   = idx & 511;
    int s   = row & (SS - 1);
    int t   = tok[row];

    float freq = expf(-(float)(d & ~1) * (9.210340371976184f / 512.0f));
    float arg  = (float)s * freq;
    float pe   = (d & 1) ? cosf(arg) : sinf(arg);

    float v = emb[(size_t)t * DD + d] * 22.62741699796952f + pe;
    out[idx] = v;
    oh[idx] = __float2half_rn(v);
}

// ================= flash attention via split-bf16 mma ======================
#define L2E 1.4426950408889634f
#define ATT_SMEM (6 * 64 * 72 * 2 + 512 * 4 + 64 * 4)

__global__ __launch_bounds__(128)
void attn_mma(const float* __restrict__ Q, int qstr,
              const float* __restrict__ K, int kstr,
              const float* __restrict__ V, int vstr,
              const int* __restrict__ tok, int causal,
              __half* __restrict__ Oh)
{
    extern __shared__ char sm[];
    __nv_bfloat16* Qh = (__nv_bfloat16*)sm;
    __nv_bfloat16* Ql = Qh + 64 * 72;
    __nv_bfloat16* Kh = Ql + 64 * 72;
    __nv_bfloat16* Kl = Kh + 64 * 72;
    __nv_bfloat16* Th = Kl + 64 * 72;
    __nv_bfloat16* Tl = Th + 64 * 72;
    int* kvm = (int*)(Tl + 64 * 72);
    int* tqv = kvm + 512;

    const int q0  = blockIdx.x * 64;
    const int h   = blockIdx.y;
    const int b   = blockIdx.z;
    const int tid = threadIdx.x;
    const int lane = tid & 31;
    const int w    = tid >> 5;

#pragma unroll
    for (int i = 0; i < 32; i++) {
        int e = tid + i * 128;
        int r = e >> 6, d = e & 63;
        float v = Q[(size_t)(b * SS + q0 + r) * qstr + h * 64 + d];
        __nv_bfloat16 hi, lo; split32(v, hi, lo);
        Qh[r * 72 + d] = hi; Ql[r * 72 + d] = lo;
    }
#pragma unroll
    for (int i = 0; i < 4; i++) {
        int e = tid + i * 128;
        kvm[e] = (tok[b * SS + e] != 0);
    }
    if (tid < 64) tqv[tid] = tok[b * SS + q0 + tid];
    __syncthreads();

    const uint32_t uQh = s2u(Qh), uKh = s2u(Kh), uTh = s2u(Th);
    const int a_row = lane & 15;
    const int a_col = (lane >> 4) * 8;
    const int b_row = (lane & 7) + ((lane >> 4) << 3);
    const int b_col = ((lane >> 3) & 1) * 8;
    const int c0    = 2 * (lane & 3);

    const int lrow0 = w * 16 + (lane >> 2);
    const int row0  = q0 + lrow0;
    const int row1  = row0 + 8;
    const int tq0   = tqv[lrow0];
    const int tq1   = tqv[lrow0 + 8];

    float m0 = -INFINITY, m1 = -INFINITY, l0 = 0.f, l1 = 0.f;
    float ao[8][4];
#pragma unroll
    for (int f = 0; f < 8; f++)
#pragma unroll
        for (int j = 0; j < 4; j++) ao[f][j] = 0.f;

    for (int kt = 0; kt < SS; kt += 64) {
#pragma unroll
        for (int i = 0; i < 32; i++) {
            int e = tid + i * 128;
            int kr = e >> 6, d = e & 63;
            __nv_bfloat16 hi, lo;
            float kvv = K[(size_t)(b * SS + kt + kr) * kstr + h * 64 + d];
            split32(kvv, hi, lo);
            Kh[kr * 72 + d] = hi; Kl[kr * 72 + d] = lo;
            float vv = V[(size_t)(b * SS + kt + kr) * vstr + h * 64 + d];
            split32(vv, hi, lo);
            Th[d * 72 + kr] = hi; Tl[d * 72 + kr] = lo;
        }
        __syncthreads();

        float s[8][4];
#pragma unroll
        for (int f = 0; f < 8; f++)
#pragma unroll
            for (int j = 0; j < 4; j++) s[f][j] = 0.f;

#pragma unroll
        for (int jp = 0; jp < 4; jp++) {
            uint32_t qh4[4], ql4[4];
            uint32_t qad = uQh + (uint32_t)(((w * 16 + a_row) * 72 + jp * 16 + a_col) * 2);
            ldsm4(qh4, qad);
            ldsm4(ql4, qad + 64 * 72 * 2);
#pragma unroll
            for (int kb = 0; kb < 4; kb++) {
                uint32_t bh[4], bl[4];
                uint32_t bad = uKh + (uint32_t)(((kb * 16 + b_row) * 72 + jp * 16 + b_col) * 2);
                ldsm4(bh, bad);
                ldsm4(bl, bad + 64 * 72 * 2);
                mma16816(s[kb * 2],     qh4, &bh[0]);
                mma16816(s[kb * 2 + 1], qh4, &bh[2]);
                mma16816(s[kb * 2],     qh4, &bl[0]);
                mma16816(s[kb * 2 + 1], qh4, &bl[2]);
                mma16816(s[kb * 2],     ql4, &bh[0]);
                mma16816(s[kb * 2 + 1], ql4, &bh[2]);
            }
        }

#pragma unroll
        for (int f = 0; f < 8; f++) {
            int kgA = kt + f * 8 + c0;
            int kgB = kgA + 1;
            bool v0A, v0B, v1A, v1B;
            if (causal) {
                v0A = tq0 && (kgA <= row0); v0B = tq0 && (kgB <= row0);
                v1A = tq1 && (kgA <= row1); v1B = tq1 && (kgB <= row1);
            } else {
                v0A = kvm[kgA]; v0B = kvm[kgB]; v1A = v0A; v1B = v0B;
            }
            s[f][0] = v0A ? s[f][0] * 0.125f : -1e9f;
            s[f][1] = v0B ? s[f][1] * 0.125f : -1e9f;
            s[f][2] = v1A ? s[f][2] * 0.125f : -1e9f;
            s[f][3] = v1B ? s[f][3] * 0.125f : -1e9f;
        }

        float mt0 = -INFINITY, mt1 = -INFINITY;
#pragma unroll
        for (int f = 0; f < 8; f++) {
            mt0 = fmaxf(mt0, fmaxf(s[f][0], s[f][1]));
            mt1 = fmaxf(mt1, fmaxf(s[f][2], s[f][3]));
        }
        mt0 = fmaxf(mt0, __shfl_xor_sync(0xffffffffu, mt0, 1));
        mt0 = fmaxf(mt0, __shfl_xor_sync(0xffffffffu, mt0, 2));
        mt1 = fmaxf(mt1, __shfl_xor_sync(0xffffffffu, mt1, 1));
        mt1 = fmaxf(mt1, __shfl_xor_sync(0xffffffffu, mt1, 2));

        float mn0 = fmaxf(m0, mt0), mn1 = fmaxf(m1, mt1);
        float r0 = exp2f((m0 - mn0) * L2E), r1 = exp2f((m1 - mn1) * L2E);
        m0 = mn0; m1 = mn1;

        uint32_t pah[4][4], pal[4][4];
        float sum0 = 0.f, sum1 = 0.f;
#pragma unroll
        for (int f = 0; f < 8; f++) {
            float p0 = exp2f((s[f][0] - m0) * L2E);
            float p1 = exp2f((s[f][1] - m0) * L2E);
            float p2 = exp2f((s[f][2] - m1) * L2E);
            float p3 = exp2f((s[f][3] - m1) * L2E);
            sum0 += p0 + p1; sum1 += p2 + p3;
            int jp = f >> 1;
            if ((f & 1) == 0) {
                packsplit(p0, p1, pah[jp][0], pal[jp][0]);
                packsplit(p2, p3, pah[jp][1], pal[jp][1]);
            } else {
                packsplit(p0, p1, pah[jp][2], pal[jp][2]);
                packsplit(p2, p3, pah[jp][3], pal[jp][3]);
            }
        }
        sum0 += __shfl_xor_sync(0xffffffffu, sum0, 1);
        sum0 += __shfl_xor_sync(0xffffffffu, sum0, 2);
        sum1 += __shfl_xor_sync(0xffffffffu, sum1, 1);
        sum1 += __shfl_xor_sync(0xffffffffu, sum1, 2);
        l0 = l0 * r0 + sum0;
        l1 = l1 * r1 + sum1;

#pragma unroll
        for (int f = 0; f < 8; f++) {
            ao[f][0] *= r0; ao[f][1] *= r0;
            ao[f][2] *= r1; ao[f][3] *= r1;
        }

#pragma unroll
        for (int jp = 0; jp < 4; jp++) {
#pragma unroll
            for (int db = 0; db < 4; db++) {
                uint32_t bh[4], bl[4];
                uint32_t bad = uTh + (uint32_t)(((db * 16 + b_row) * 72 + jp * 16 + b_col) * 2);
                ldsm4(bh, bad);
                ldsm4(bl, bad + 64 * 72 * 2);
                mma16816(ao[db * 2],     pah[jp], &bh[0]);
                mma16816(ao[db * 2 + 1], pah[jp], &bh[2]);
                mma16816(ao[db * 2],     pah[jp], &bl[0]);
                mma16816(ao[db * 2 + 1], pah[jp], &bl[2]);
                mma16816(ao[db * 2],     pal[jp], &bh[0]);
                mma16816(ao[db * 2 + 1], pal[jp], &bh[2]);
            }
        }
        __syncthreads();
    }

    float il0 = 1.f / l0, il1 = 1.f / l1;
    size_t gr0 = (size_t)(b * SS + row0) * DD + h * 64;
    size_t gr1 = (size_t)(b * SS + row1) * DD + h * 64;
#pragma unroll
    for (int f = 0; f < 8; f++) {
        int d = f * 8 + c0;
        *(uint32_t*)&Oh[gr0 + d] = pack2h(ao[f][0] * il0, ao[f][1] * il0);
        *(uint32_t*)&Oh[gr1 + d] = pack2h(ao[f][2] * il1, ao[f][3] * il1);
    }
}

// ---------------- residual + LayerNorm: warp-per-row -----------------------
__global__ __launch_bounds__(256)
void ln_res_kernel(const float* __restrict__ t, float* __restrict__ x,
                   const float* __restrict__ s, const float* __restrict__ b,
                   __half* __restrict__ xh)
{
    const int w    = threadIdx.x >> 5;
    const int lane = threadIdx.x & 31;
    const int row  = blockIdx.x * 8 + w;

    const float4* tp = (const float4*)(t + (size_t)row * 512);
    float4*       xp = (float4*)(x + (size_t)row * 512);
    const float4* sp = (const float4*)s;
    const float4* bp = (const float4*)b;

    float4 u[4];
    float sum = 0.f;
#pragma unroll
    for (int j = 0; j < 4; j++) {
        float4 a = tp[j * 32 + lane];
        float4 c = xp[j * 32 + lane];
        u[j] = make_float4(a.x + c.x, a.y + c.y, a.z + c.z, a.w + c.w);
        sum += u[j].x + u[j].y + u[j].z + u[j].w;
    }
#pragma unroll
    for (int o = 16; o; o >>= 1) sum += __shfl_xor_sync(0xffffffffu, sum, o);
    float mean = sum * (1.0f / 512.0f);

    float sq = 0.f;
#pragma unroll
    for (int j = 0; j < 4; j++) {
        float dx = u[j].x - mean, dy = u[j].y - mean;
        float dz = u[j].z - mean, dw = u[j].w - mean;
        sq += dx * dx + dy * dy + dz * dz + dw * dw;
    }
#pragma unroll
    for (int o = 16; o; o >>= 1) sq += __shfl_xor_sync(0xffffffffu, sq, o);
    float inv = rsqrtf(sq * (1.0f / 512.0f) + 1e-5f);

#pragma unroll
    for (int j = 0; j < 4; j++) {
        float4 sc = sp[j * 32 + lane];
        float4 bb = bp[j * 32 + lane];
        float4 o;
        o.x = (u[j].x - mean) * inv * sc.x + bb.x;
        o.y = (u[j].y - mean) * inv * sc.y + bb.y;
        o.z = (u[j].z - mean) * inv * sc.z + bb.z;
        o.w = (u[j].w - mean) * inv * sc.w + bb.w;
        xp[j * 32 + lane] = o;
        size_t e = (size_t)row * 512 + (size_t)(j * 32 + lane) * 4;
        *(uint2*)&xh[e] = make_uint2(pack2h(o.x, o.y), pack2h(o.z, o.w));
    }
}

// ---------------- host orchestration ---------------------------------------
static __half *h_wh, *h_wl, *h_ah, *h_xh, *h_yh;

static inline void run_gemm(const __half* A, size_t woff, const float* bias,
                            float* C, int M, int N, int K)
{
    if ((N & 255) == 0 && N >= 1024) {
        dim3 g(N / 256, M / 128);
        gemm_tcw<<<g, 256, WSM_TOTAL>>>(A, h_wh + woff, h_wl + woff, bias, C,
                                        nullptr, M, N, K, 0);
    } else {
        dim3 g(N / 128, M / 128);
        gemm_tc<<<g, 256, SM_TOTAL>>>(A, h_wh + woff, h_wl + woff, bias, C,
                                      nullptr, M, N, K, 0);
    }
}
static inline void run_gemm_relu(const __half* A, size_t woff, const float* bias,
                                 __half* Oh, int M, int N, int K)
{
    if ((N & 255) == 0 && N >= 1024) {
        dim3 g(N / 256, M / 128);
        gemm_tcw<<<g, 256, WSM_TOTAL>>>(A, h_wh + woff, h_wl + woff, bias, nullptr,
                                        Oh, M, N, K, 1);
    } else {
        dim3 g(N / 128, M / 128);
        gemm_tc<<<g, 256, SM_TOTAL>>>(A, h_wh + woff, h_wl + woff, bias, nullptr,
                                      Oh, M, N, K, 1);
    }
}

extern "C" void kernel_launch(void* const* d_in, const int* in_sizes, int n_in,
                              void* d_out, int out_size)
{
    const int*   src     = (const int*)  d_in[0];
    const int*   tgt     = (const int*)  d_in[1];
    const float* src_emb = (const float*)d_in[2];
    const float* tgt_emb = (const float*)d_in[3];
    const float* eaw     = (const float*)d_in[4];
    const float* eab     = (const float*)d_in[5];
    const float* els     = (const float*)d_in[6];
    const float* elb     = (const float*)d_in[7];
    const float* ef1     = (const float*)d_in[8];
    const float* eb1     = (const float*)d_in[9];
    const float* ef2     = (const float*)d_in[10];
    const float* eb2     = (const float*)d_in[11];
    const float* daw     = (const float*)d_in[12];
    const float* dab     = (const float*)d_in[13];
    const float* dls     = (const float*)d_in[14];
    const float* dlb     = (const float*)d_in[15];
    const float* df1     = (const float*)d_in[16];
    const float* db1     = (const float*)d_in[17];
    const float* df2     = (const float*)d_in[18];
    const float* db2     = (const float*)d_in[19];
    const float* fcw     = (const float*)d_in[20];
    const float* fcb     = (const float*)d_in[21];
    float*       out     = (float*)d_out;

    float *x, *y, *qkv, *t;
    cudaGetSymbolAddress((void**)&x,   g_x);
    cudaGetSymbolAddress((void**)&y,   g_y);
    cudaGetSymbolAddress((void**)&qkv, g_qkv);
    cudaGetSymbolAddress((void**)&t,   g_t);
    cudaGetSymbolAddress((void**)&h_wh, g_wh);
    cudaGetSymbolAddress((void**)&h_wl, g_wl);
    cudaGetSymbolAddress((void**)&h_ah, g_ah);
    cudaGetSymbolAddress((void**)&h_xh, g_xh);
    cudaGetSymbolAddress((void**)&h_yh, g_yh);

    cudaFuncSetAttribute(gemm_tc,  cudaFuncAttributeMaxDynamicSharedMemorySize, SM_TOTAL);
    cudaFuncSetAttribute(gemm_tcw, cudaFuncAttributeMaxDynamicSharedMemorySize, WSM_TOTAL);
    cudaFuncSetAttribute(attn_mma, cudaFuncAttributeMaxDynamicSharedMemorySize, ATT_SMEM);

    // ---- weight prep: ONE launch ----
    {
        dim3 bdim(32, 8);
        wconv_all<<<WCONV_BLOCKS, bdim>>>(eaw, daw, ef1, ef2, df1, df2, fcw, h_wh, h_wl);
    }

    // embeddings + positional encoding (+ fp16 copy)
    embed_kernel<<<(NT * DD) / 256, 256>>>(src, src_emb, x, h_xh);
    embed_kernel<<<(NT * DD) / 256, 256>>>(tgt, tgt_emb, y, h_yh);

    dim3 ag(SS / 64, NH, BB);
    float* kvbuf = qkv + (size_t)NT * 512;

    // ---------------- encoder ----------------
    for (int L = 0; L < NLAY; L++) {
        size_t w0 = OFF_EAW + (size_t)(L * 4) * WSZ;
        const float* Bz = eab + (size_t)L * 4 * DD;

        run_gemm(h_xh, w0, Bz, qkv, NT, 1536, DD);
        attn_mma<<<ag, 128, ATT_SMEM>>>(qkv, 1536, qkv + 512, 1536, qkv + 1024, 1536,
                                        src, 0, h_ah);
        run_gemm(h_ah, w0 + 3 * WSZ, Bz + 3 * DD, t, NT, DD, DD);
        ln_res_kernel<<<NT / 8, 256>>>(t, x, els + (size_t)(L * 2 + 0) * DD,
                                       elb + (size_t)(L * 2 + 0) * DD, h_xh);

        run_gemm_relu(h_xh, OFF_EF1 + (size_t)L * DD * DFF,
                      eb1 + (size_t)L * DFF, h_ah, NT, DFF, DD);
        run_gemm(h_ah, OFF_EF2 + (size_t)L * DD * DFF, eb2 + (size_t)L * DD,
                 t, NT, DD, DFF);
        ln_res_kernel<<<NT / 8, 256>>>(t, x, els + (size_t)(L * 2 + 1) * DD,
                                       elb + (size_t)(L * 2 + 1) * DD, h_xh);
    }

    // ---------------- decoder ----------------
    for (int L = 0; L < NLAY; L++) {
        size_t w0 = OFF_DAW + (size_t)(L * 8) * WSZ;
        const float* Bz = dab + (size_t)L * 8 * DD;

        run_gemm(h_yh, w0, Bz, qkv, NT, 1536, DD);
        attn_mma<<<ag, 128, ATT_SMEM>>>(qkv, 1536, qkv + 512, 1536, qkv + 1024, 1536,
                                        tgt, 1, h_ah);
        run_gemm(h_ah, w0 + 3 * WSZ, Bz + 3 * DD, t, NT, DD, DD);
        ln_res_kernel<<<NT / 8, 256>>>(t, y, dls + (size_t)(L * 3 + 0) * DD,
                                       dlb + (size_t)(L * 3 + 0) * DD, h_yh);

        run_gemm(h_yh, w0 + 4 * WSZ, Bz + 4 * DD, qkv, NT, DD, DD);
        run_gemm(h_xh, w0 + 5 * WSZ, Bz + 5 * DD, kvbuf, NT, 1024, DD);
        attn_mma<<<ag, 128, ATT_SMEM>>>(qkv, 512, kvbuf, 1024, kvbuf + 512, 1024,
                                        src, 0, h_ah);
        run_gemm(h_ah, w0 + 7 * WSZ, Bz + 7 * DD, t, NT, DD, DD);
        ln_res_kernel<<<NT / 8, 256>>>(t, y, dls + (size_t)(L * 3 + 1) * DD,
                                       dlb + (size_t)(L * 3 + 1) * DD, h_yh);

        run_gemm_relu(h_yh, OFF_DF1 + (size_t)L * DD * DFF,
                      db1 + (size_t)L * DFF, h_ah, NT, DFF, DD);
        run_gemm(h_ah, OFF_DF2 + (size_t)L * DD * DFF, db2 + (size_t)L * DD,
                 t, NT, DD, DFF);
        ln_res_kernel<<<NT / 8, 256>>>(t, y, dls + (size_t)(L * 3 + 2) * DD,
                                       dlb + (size_t)(L * 3 + 2) * DD, h_yh);
    }

    // final projection to vocab
    run_gemm(h_yh, OFF_FC, fcb, out, NT, VOCAB, DD);
}